// round 13
// baseline (speedup 1.0000x reference)
#include <cuda_runtime.h>
#include <cstdint>

#define NN   20000
#define RR   32
#define EMB  16
#define HID  128
#define NE   600000
#define NRB  (NN*RR)          // 640000 (rel, dst) buckets, r-major: b = r*NN + dst
#define NTILE 313             // ceil(NN/64)

// ---- scratch (device globals; no allocation anywhere) ----
__device__ int   g_bcnt[NRB];     // edges per (rel, dst) bucket
__device__ int   g_cur [NRB];     // fill cursor
__device__ int   g_boff[NRB];     // exclusive prefix (CSR offsets)
__device__ int   g_bsum[1024];    // scan partials
__device__ int   g_bsumoff[1024];
__device__ int   g_esrc[NE];      // src ids grouped by bucket
__device__ float g_h1  [NN*HID];  // layer-1 output (10 MB, L2-resident)
__device__ int   g_ccnt[RR];      // nonempty-bucket count per relation
__device__ int   g_rows[RR*NN];   // per-rel compacted dst lists

// ---------------------------------------------------------------- helpers
__device__ __forceinline__ uint32_t f2tf32(float f) {
    uint32_t r;
    asm("cvt.rna.tf32.f32 %0, %1;" : "=r"(r) : "f"(f));
    return r;
}

__device__ __forceinline__ void mma_tf32(float* d, const uint32_t* a, const uint32_t* b) {
    asm volatile("mma.sync.aligned.m16n8k8.row.col.f32.tf32.tf32.f32 "
                 "{%0,%1,%2,%3}, {%4,%5,%6,%7}, {%8,%9}, {%0,%1,%2,%3};"
                 : "+f"(d[0]), "+f"(d[1]), "+f"(d[2]), "+f"(d[3])
                 : "r"(a[0]), "r"(a[1]), "r"(a[2]), "r"(a[3]),
                   "r"(b[0]), "r"(b[1]));
}

// ---------------------------------------------------------------- CSR build
__global__ void k_zero() {
    int i = blockIdx.x * blockDim.x + threadIdx.x;
    if (i < NRB) { g_bcnt[i] = 0; g_cur[i] = 0; }
    if (i < RR)  g_ccnt[i] = 0;
}

__global__ void k_count(const int* __restrict__ ei, const int* __restrict__ et) {
    int e = blockIdx.x * blockDim.x + threadIdx.x;
    if (e >= NE) return;
    int dst = ei[NE + e];
    int r   = et[e];
    atomicAdd(&g_bcnt[r*NN + dst], 1);
}

// exclusive scan over NRB = 625 * 1024 exactly
__global__ void k_scan1() {
    __shared__ int sh[256];
    int tid  = threadIdx.x;
    int base = blockIdx.x * 1024 + tid * 4;
    int v0 = g_bcnt[base+0], v1 = g_bcnt[base+1];
    int v2 = g_bcnt[base+2], v3 = g_bcnt[base+3];
    int tsum = v0 + v1 + v2 + v3;
    sh[tid] = tsum;
    __syncthreads();
    for (int off = 1; off < 256; off <<= 1) {
        int t = (tid >= off) ? sh[tid - off] : 0;
        __syncthreads();
        sh[tid] += t;
        __syncthreads();
    }
    int excl = sh[tid] - tsum;
    g_boff[base+0] = excl;
    g_boff[base+1] = excl + v0;
    g_boff[base+2] = excl + v0 + v1;
    g_boff[base+3] = excl + v0 + v1 + v2;
    if (tid == 255) g_bsum[blockIdx.x] = sh[255];
}

__global__ void k_scan2() {
    __shared__ int sh[1024];
    int tid = threadIdx.x;
    int v = (tid < 625) ? g_bsum[tid] : 0;
    sh[tid] = v;
    __syncthreads();
    for (int off = 1; off < 1024; off <<= 1) {
        int t = (tid >= off) ? sh[tid - off] : 0;
        __syncthreads();
        sh[tid] += t;
        __syncthreads();
    }
    if (tid < 625) g_bsumoff[tid] = sh[tid] - v;
}

__global__ void k_scan3() {
    int tid  = threadIdx.x;
    int add  = g_bsumoff[blockIdx.x];
    int base = blockIdx.x * 1024 + tid * 4;
    g_boff[base+0] += add; g_boff[base+1] += add;
    g_boff[base+2] += add; g_boff[base+3] += add;
}

__global__ void k_fill(const int* __restrict__ ei, const int* __restrict__ et) {
    int e = blockIdx.x * blockDim.x + threadIdx.x;
    if (e >= NE) return;
    int src = ei[e];
    int dst = ei[NE + e];
    int r   = et[e];
    int b   = r*NN + dst;
    int p   = atomicAdd(&g_cur[b], 1);
    g_esrc[g_boff[b] + p] = src;
}

// ---------------------------------------------------------------- compact nonempty buckets
// warp-aggregated: NN % 32 == 0 so a warp never straddles a relation boundary.
__global__ void k_compact() {
    int i = blockIdx.x * blockDim.x + threadIdx.x;
    if (i >= NRB) return;
    int r = i / NN, d = i - r*NN;
    bool f = g_bcnt[i] > 0;
    unsigned mask = __ballot_sync(0xffffffffu, f);
    if (mask == 0) return;
    int lane = threadIdx.x & 31;
    int leader = __ffs(mask) - 1;
    int base = 0;
    if (lane == leader) base = atomicAdd(&g_ccnt[r], __popc(mask));
    base = __shfl_sync(0xffffffffu, base, leader);
    if (f) {
        int rank = __popc(mask & ((1u << lane) - 1));
        g_rows[r*NN + base + rank] = d;
    }
}

// ---------------------------------------------------------------- layer-1 root: g_h1 = x @ root1 + b1 (no relu yet)
__global__ void __launch_bounds__(128)
k_root1(const float* __restrict__ x, const float* __restrict__ r1,
        const float* __restrict__ b1) {
    __shared__ uint32_t As[64][20];
    __shared__ uint32_t Bs[16][136];
    int m0  = blockIdx.x * 64;
    int tid = threadIdx.x;
    int wid = tid >> 5, lane = tid & 31;
    int gr  = lane >> 2, tg = lane & 3;
    int row = tid >> 1, hf = tid & 1;
    int n   = m0 + row;
    int bk  = tid >> 3, bc = (tid & 7) << 4;

    float c[4][4][4];
    #pragma unroll
    for (int i = 0; i < 4; i++)
        #pragma unroll
        for (int j = 0; j < 4; j++)
            #pragma unroll
            for (int q = 0; q < 4; q++) c[i][j][q] = 0.f;

    float4 s0 = make_float4(0.f,0.f,0.f,0.f), s1 = s0;
    if (n < NN) {
        const float4* p = (const float4*)&x[n*EMB + hf*8];
        s0 = p[0]; s1 = p[1];
    }
    *(uint4*)&As[row][hf*8    ] = make_uint4(f2tf32(s0.x), f2tf32(s0.y), f2tf32(s0.z), f2tf32(s0.w));
    *(uint4*)&As[row][hf*8 + 4] = make_uint4(f2tf32(s1.x), f2tf32(s1.y), f2tf32(s1.z), f2tf32(s1.w));
    #pragma unroll
    for (int i = 0; i < 4; i++) {
        float4 u = *(const float4*)&r1[bk*HID + bc + i*4];
        *(uint4*)&Bs[bk][bc + i*4] = make_uint4(f2tf32(u.x), f2tf32(u.y), f2tf32(u.z), f2tf32(u.w));
    }
    __syncthreads();

    #pragma unroll
    for (int kc = 0; kc < 2; ++kc) {
        int k0 = kc << 3;
        uint32_t a[4][4], b[4][2];
        #pragma unroll
        for (int mt = 0; mt < 4; ++mt) {
            int mr = mt*16;
            a[mt][0] = As[mr+gr  ][k0+tg  ];
            a[mt][1] = As[mr+gr+8][k0+tg  ];
            a[mt][2] = As[mr+gr  ][k0+tg+4];
            a[mt][3] = As[mr+gr+8][k0+tg+4];
        }
        #pragma unroll
        for (int nt = 0; nt < 4; ++nt) {
            int nc = wid*32 + nt*8 + gr;
            b[nt][0] = Bs[k0+tg  ][nc];
            b[nt][1] = Bs[k0+tg+4][nc];
        }
        #pragma unroll
        for (int mt = 0; mt < 4; ++mt)
            #pragma unroll
            for (int nt = 0; nt < 4; ++nt)
                mma_tf32(c[mt][nt], a[mt], b[nt]);
    }

    #pragma unroll
    for (int mt = 0; mt < 4; ++mt) {
        #pragma unroll
        for (int eh = 0; eh < 2; ++eh) {
            int rn = m0 + mt*16 + gr + eh*8;
            if (rn < NN) {
                #pragma unroll
                for (int nt = 0; nt < 4; ++nt) {
                    int col = wid*32 + nt*8 + tg*2;
                    *(float2*)&g_h1[rn*HID + col] =
                        make_float2(c[mt][nt][eh*2+0] + b1[col],
                                    c[mt][nt][eh*2+1] + b1[col+1]);
                }
            }
        }
    }
}

// ---------------------------------------------------------------- layer-1 relation GEMM (compacted)
// grid (313, 32): g_h1[dst] += mean_x(bucket) @ W1[rel]  via atomicAdd.
__global__ void __launch_bounds__(128)
k_l1agg(const float* __restrict__ x, const float* __restrict__ W1) {
    __shared__ uint32_t As[64][20];
    __shared__ uint32_t Bs[16][136];
    int rel = blockIdx.y;
    int m0  = blockIdx.x * 64;
    int cnt = g_ccnt[rel];
    if (m0 >= cnt) return;
    const int* rows = g_rows + rel*NN;

    int tid = threadIdx.x;
    int wid = tid >> 5, lane = tid & 31;
    int gr  = lane >> 2, tg = lane & 3;
    int row = tid >> 1, hf = tid & 1;
    int idx = m0 + row;
    int d   = (idx < cnt) ? rows[idx] : -1;
    int bk  = tid >> 3, bc = (tid & 7) << 4;

    float c[4][4][4];
    #pragma unroll
    for (int i = 0; i < 4; i++)
        #pragma unroll
        for (int j = 0; j < 4; j++)
            #pragma unroll
            for (int q = 0; q < 4; q++) c[i][j][q] = 0.f;

    // ---- A build: mean of x[src] over bucket (rel, d)
    float4 s0 = make_float4(0.f,0.f,0.f,0.f), s1 = s0;
    if (d >= 0) {
        int b = rel*NN + d;
        int deg = g_bcnt[b], off = g_boff[b];
        for (int j = 0; j < deg; ++j) {
            int src = g_esrc[off + j];
            const float4* p = (const float4*)&x[src*EMB + hf*8];
            float4 a = p[0], bq = p[1];
            s0.x += a.x;  s0.y += a.y;  s0.z += a.z;  s0.w += a.w;
            s1.x += bq.x; s1.y += bq.y; s1.z += bq.z; s1.w += bq.w;
        }
        float iv = 1.f / (float)deg;
        s0.x*=iv; s0.y*=iv; s0.z*=iv; s0.w*=iv;
        s1.x*=iv; s1.y*=iv; s1.z*=iv; s1.w*=iv;
    }
    *(uint4*)&As[row][hf*8    ] = make_uint4(f2tf32(s0.x), f2tf32(s0.y), f2tf32(s0.z), f2tf32(s0.w));
    *(uint4*)&As[row][hf*8 + 4] = make_uint4(f2tf32(s1.x), f2tf32(s1.y), f2tf32(s1.z), f2tf32(s1.w));
    #pragma unroll
    for (int i = 0; i < 4; i++) {
        float4 u = *(const float4*)&W1[rel*(EMB*HID) + bk*HID + bc + i*4];
        *(uint4*)&Bs[bk][bc + i*4] = make_uint4(f2tf32(u.x), f2tf32(u.y), f2tf32(u.z), f2tf32(u.w));
    }
    __syncthreads();

    #pragma unroll
    for (int kc = 0; kc < 2; ++kc) {
        int k0 = kc << 3;
        uint32_t a[4][4], b[4][2];
        #pragma unroll
        for (int mt = 0; mt < 4; ++mt) {
            int mr = mt*16;
            a[mt][0] = As[mr+gr  ][k0+tg  ];
            a[mt][1] = As[mr+gr+8][k0+tg  ];
            a[mt][2] = As[mr+gr  ][k0+tg+4];
            a[mt][3] = As[mr+gr+8][k0+tg+4];
        }
        #pragma unroll
        for (int nt = 0; nt < 4; ++nt) {
            int nc = wid*32 + nt*8 + gr;
            b[nt][0] = Bs[k0+tg  ][nc];
            b[nt][1] = Bs[k0+tg+4][nc];
        }
        #pragma unroll
        for (int mt = 0; mt < 4; ++mt)
            #pragma unroll
            for (int nt = 0; nt < 4; ++nt)
                mma_tf32(c[mt][nt], a[mt], b[nt]);
    }

    #pragma unroll
    for (int mt = 0; mt < 4; ++mt) {
        #pragma unroll
        for (int eh = 0; eh < 2; ++eh) {
            int i2 = m0 + mt*16 + gr + eh*8;
            if (i2 < cnt) {
                int d2 = rows[i2];
                float* ob = &g_h1[d2*HID];
                #pragma unroll
                for (int nt = 0; nt < 4; ++nt) {
                    int col = wid*32 + nt*8 + tg*2;
                    atomicAdd(&ob[col],   c[mt][nt][eh*2+0]);
                    atomicAdd(&ob[col+1], c[mt][nt][eh*2+1]);
                }
            }
        }
    }
}

// ---------------------------------------------------------------- relu in place on g_h1
__global__ void k_relu() {
    int i = blockIdx.x * blockDim.x + threadIdx.x;
    if (i >= (NN*HID)/4) return;
    float4 v = ((float4*)g_h1)[i];
    v.x = fmaxf(v.x, 0.f); v.y = fmaxf(v.y, 0.f);
    v.z = fmaxf(v.z, 0.f); v.w = fmaxf(v.w, 0.f);
    ((float4*)g_h1)[i] = v;
}

// ---------------------------------------------------------------- layer-2 root: out = h1 @ root2 + b2
__global__ void __launch_bounds__(128)
k_root(const float* __restrict__ r2, const float* __restrict__ b2,
       float* __restrict__ out) {
    __shared__ uint32_t As[64][132];
    __shared__ uint32_t Bs[16][136];
    int m0  = blockIdx.x * 64;
    int tid = threadIdx.x;
    int wid = tid >> 5, lane = tid & 31;
    int gr  = lane >> 2, tg = lane & 3;
    int row = tid >> 1, hf = tid & 1;
    int n   = m0 + row;
    int bk  = tid >> 3, bc = (tid & 7) << 4;

    float c[4][4][4];
    #pragma unroll
    for (int i = 0; i < 4; i++)
        #pragma unroll
        for (int j = 0; j < 4; j++)
            #pragma unroll
            for (int q = 0; q < 4; q++) c[i][j][q] = 0.f;

    #pragma unroll
    for (int hp = 0; hp < 2; ++hp) {
        int cbase = hf*64 + hp*32;
        float4 s[8];
        #pragma unroll
        for (int i = 0; i < 8; i++) s[i] = make_float4(0.f,0.f,0.f,0.f);
        if (n < NN) {
            const float4* p = (const float4*)&g_h1[n*HID + cbase];
            #pragma unroll
            for (int i = 0; i < 8; i++) s[i] = p[i];
        }
        #pragma unroll
        for (int i = 0; i < 8; i++)
            *(uint4*)&As[row][cbase + i*4] =
                make_uint4(f2tf32(s[i].x), f2tf32(s[i].y), f2tf32(s[i].z), f2tf32(s[i].w));
    }

    float4 u[4];
    #pragma unroll
    for (int i = 0; i < 4; i++) u[i] = *(const float4*)&r2[bk*HID + bc + i*4];

    for (int step = 0; step < 8; ++step) {
        __syncthreads();
        #pragma unroll
        for (int i = 0; i < 4; i++)
            *(uint4*)&Bs[bk][bc + i*4] = make_uint4(f2tf32(u[i].x), f2tf32(u[i].y), f2tf32(u[i].z), f2tf32(u[i].w));
        if (step < 7) {
            const float* nx = r2 + (step+1)*16*HID;
            #pragma unroll
            for (int i = 0; i < 4; i++) u[i] = *(const float4*)&nx[bk*HID + bc + i*4];
        }
        __syncthreads();
        #pragma unroll
        for (int kc = 0; kc < 2; ++kc) {
            int k0 = kc << 3;
            int ac = step*16 + k0;
            uint32_t a[4][4], b[4][2];
            #pragma unroll
            for (int mt = 0; mt < 4; ++mt) {
                int mr = mt*16;
                a[mt][0] = As[mr+gr  ][ac+tg  ];
                a[mt][1] = As[mr+gr+8][ac+tg  ];
                a[mt][2] = As[mr+gr  ][ac+tg+4];
                a[mt][3] = As[mr+gr+8][ac+tg+4];
            }
            #pragma unroll
            for (int nt = 0; nt < 4; ++nt) {
                int nc = wid*32 + nt*8 + gr;
                b[nt][0] = Bs[k0+tg  ][nc];
                b[nt][1] = Bs[k0+tg+4][nc];
            }
            #pragma unroll
            for (int mt = 0; mt < 4; ++mt)
                #pragma unroll
                for (int nt = 0; nt < 4; ++nt)
                    mma_tf32(c[mt][nt], a[mt], b[nt]);
        }
    }

    #pragma unroll
    for (int mt = 0; mt < 4; ++mt) {
        #pragma unroll
        for (int eh = 0; eh < 2; ++eh) {
            int rn = m0 + mt*16 + gr + eh*8;
            if (rn < NN) {
                #pragma unroll
                for (int nt = 0; nt < 4; ++nt) {
                    int col = wid*32 + nt*8 + tg*2;
                    *(float2*)&out[rn*HID + col] =
                        make_float2(c[mt][nt][eh*2+0] + b2[col],
                                    c[mt][nt][eh*2+1] + b2[col+1]);
                }
            }
        }
    }
}

// ---------------------------------------------------------------- layer-2 relation GEMM (compacted)
__global__ void __launch_bounds__(128)
k_l2agg(const float* __restrict__ W2, float* __restrict__ out) {
    __shared__ uint32_t As[64][132];
    __shared__ uint32_t Bs[16][136];
    int rel = blockIdx.y;
    int m0  = blockIdx.x * 64;
    int cnt = g_ccnt[rel];
    if (m0 >= cnt) return;
    const int* rows = g_rows + rel*NN;

    int tid = threadIdx.x;
    int wid = tid >> 5, lane = tid & 31;
    int gr  = lane >> 2, tg = lane & 3;
    int row = tid >> 1, hf = tid & 1;
    int idx = m0 + row;
    int d   = (idx < cnt) ? rows[idx] : -1;
    int bk  = tid >> 3, bc = (tid & 7) << 4;

    float c[4][4][4];
    #pragma unroll
    for (int i = 0; i < 4; i++)
        #pragma unroll
        for (int j = 0; j < 4; j++)
            #pragma unroll
            for (int q = 0; q < 4; q++) c[i][j][q] = 0.f;

    int deg = 0, off = 0;
    if (d >= 0) { int b = rel*NN + d; deg = g_bcnt[b]; off = g_boff[b]; }
    #pragma unroll
    for (int hp = 0; hp < 2; ++hp) {
        int cbase = hf*64 + hp*32;
        float4 s[8];
        #pragma unroll
        for (int i = 0; i < 8; i++) s[i] = make_float4(0.f,0.f,0.f,0.f);
        for (int j = 0; j < deg; ++j) {
            int src = g_esrc[off + j];
            const float4* p = (const float4*)&g_h1[src*HID + cbase];
            #pragma unroll
            for (int i = 0; i < 8; i++) {
                float4 a = p[i];
                s[i].x += a.x; s[i].y += a.y; s[i].z += a.z; s[i].w += a.w;
            }
        }
        if (deg > 0) {
            float iv = 1.f / (float)deg;
            #pragma unroll
            for (int i = 0; i < 8; i++) { s[i].x*=iv; s[i].y*=iv; s[i].z*=iv; s[i].w*=iv; }
        }
        #pragma unroll
        for (int i = 0; i < 8; i++)
            *(uint4*)&As[row][cbase + i*4] =
                make_uint4(f2tf32(s[i].x), f2tf32(s[i].y), f2tf32(s[i].z), f2tf32(s[i].w));
    }

    const float* Bbase = W2 + rel*(HID*HID);
    float4 u[4];
    #pragma unroll
    for (int i = 0; i < 4; i++) u[i] = *(const float4*)&Bbase[bk*HID + bc + i*4];

    for (int step = 0; step < 8; ++step) {
        __syncthreads();
        #pragma unroll
        for (int i = 0; i < 4; i++)
            *(uint4*)&Bs[bk][bc + i*4] = make_uint4(f2tf32(u[i].x), f2tf32(u[i].y), f2tf32(u[i].z), f2tf32(u[i].w));
        if (step < 7) {
            const float* nx = Bbase + (step+1)*16*HID;
            #pragma unroll
            for (int i = 0; i < 4; i++) u[i] = *(const float4*)&nx[bk*HID + bc + i*4];
        }
        __syncthreads();
        #pragma unroll
        for (int kc = 0; kc < 2; ++kc) {
            int k0 = kc << 3;
            int ac = step*16 + k0;
            uint32_t a[4][4], b[4][2];
            #pragma unroll
            for (int mt = 0; mt < 4; ++mt) {
                int mr = mt*16;
                a[mt][0] = As[mr+gr  ][ac+tg  ];
                a[mt][1] = As[mr+gr+8][ac+tg  ];
                a[mt][2] = As[mr+gr  ][ac+tg+4];
                a[mt][3] = As[mr+gr+8][ac+tg+4];
            }
            #pragma unroll
            for (int nt = 0; nt < 4; ++nt) {
                int nc = wid*32 + nt*8 + gr;
                b[nt][0] = Bs[k0+tg  ][nc];
                b[nt][1] = Bs[k0+tg+4][nc];
            }
            #pragma unroll
            for (int mt = 0; mt < 4; ++mt)
                #pragma unroll
                for (int nt = 0; nt < 4; ++nt)
                    mma_tf32(c[mt][nt], a[mt], b[nt]);
        }
    }

    #pragma unroll
    for (int mt = 0; mt < 4; ++mt) {
        #pragma unroll
        for (int eh = 0; eh < 2; ++eh) {
            int i2 = m0 + mt*16 + gr + eh*8;
            if (i2 < cnt) {
                int d2 = rows[i2];
                float* ob = &out[d2*HID];
                #pragma unroll
                for (int nt = 0; nt < 4; ++nt) {
                    int col = wid*32 + nt*8 + tg*2;
                    atomicAdd(&ob[col],   c[mt][nt][eh*2+0]);
                    atomicAdd(&ob[col+1], c[mt][nt][eh*2+1]);
                }
            }
        }
    }
}

// ---------------------------------------------------------------- launch
extern "C" void kernel_launch(void* const* d_in, const int* in_sizes, int n_in,
                              void* d_out, int out_size) {
    const int* ei    = (const int*)d_in[0];            // edge_index [2, E] int32
    const int* et    = (const int*)d_in[1];            // edge_type  [E]    int32
    const float* x   = (const float*)d_in[2];          // node_emb [N, 16]
    const float* W1  = (const float*)d_in[3];          // [32, 16, 128]
    const float* r1  = (const float*)d_in[4];          // [16, 128]
    const float* b1  = (const float*)d_in[5];          // [128]
    const float* W2  = (const float*)d_in[6];          // [32, 128, 128]
    const float* r2  = (const float*)d_in[7];          // [128, 128]
    const float* b2  = (const float*)d_in[8];          // [128]
    float* out = (float*)d_out;                        // [20000, 128]

    k_zero   <<<(NRB + 255)/256, 256>>>();
    k_count  <<<(NE + 255)/256, 256>>>(ei, et);
    k_scan1  <<<625, 256>>>();
    k_scan2  <<<1, 1024>>>();
    k_scan3  <<<625, 256>>>();
    k_fill   <<<(NE + 255)/256, 256>>>(ei, et);
    k_compact<<<(NRB + 255)/256, 256>>>();
    k_root1  <<<NTILE, 128>>>(x, r1, b1);
    dim3 g1(NTILE, RR);
    k_l1agg  <<<g1, 128>>>(x, W1);
    k_relu   <<<(NN*HID/4 + 255)/256, 256>>>();
    k_root   <<<NTILE, 128>>>(r2, b2, out);
    dim3 g2(NTILE, RR);
    k_l2agg  <<<g2, 128>>>(W2, out);
}

// round 14
// speedup vs baseline: 1.3341x; 1.3341x over previous
#include <cuda_runtime.h>
#include <cstdint>

#define NN   20000
#define RR   32
#define EMB  16
#define HID  128
#define NE   600000
#define NRB  (NN*RR)          // 640000 (rel, dst) buckets, r-major: b = r*NN + dst
#define NTILE 313             // ceil(NN/64)

// ---- scratch (device globals; no allocation anywhere) ----
__device__ int   g_bcnt[NRB];     // edges per (rel, dst) bucket
__device__ int   g_cur [NRB];     // fill cursor
__device__ int   g_boff[NRB+1];   // exclusive prefix (CSR offsets) + sentinel NE
__device__ int   g_bsum[1024];    // scan partials
__device__ int   g_bsumoff[1024];
__device__ int   g_esrc[NE];      // src ids grouped by bucket
__device__ int   g_edst[NE];      // dst ids grouped by bucket (parallel to g_esrc)
__device__ float g_h1  [NN*HID];  // layer-1 output (10 MB, L2-resident)
__device__ int   g_ccnt[RR];      // nonempty-bucket count per relation
__device__ int   g_rows[RR*NN];   // per-rel compacted dst lists

// ---------------------------------------------------------------- helpers
__device__ __forceinline__ uint32_t f2tf32(float f) {
    uint32_t r;
    asm("cvt.rna.tf32.f32 %0, %1;" : "=r"(r) : "f"(f));
    return r;
}

__device__ __forceinline__ void mma_tf32(float* d, const uint32_t* a, const uint32_t* b) {
    asm volatile("mma.sync.aligned.m16n8k8.row.col.f32.tf32.tf32.f32 "
                 "{%0,%1,%2,%3}, {%4,%5,%6,%7}, {%8,%9}, {%0,%1,%2,%3};"
                 : "+f"(d[0]), "+f"(d[1]), "+f"(d[2]), "+f"(d[3])
                 : "r"(a[0]), "r"(a[1]), "r"(a[2]), "r"(a[3]),
                   "r"(b[0]), "r"(b[1]));
}

__device__ __forceinline__ void red_add_v2(float* p, float a, float b) {
    asm volatile("red.global.add.v2.f32 [%0], {%1, %2};"
                 :: "l"(p), "f"(a), "f"(b) : "memory");
}

// ---------------------------------------------------------------- CSR build
__global__ void k_zero() {
    int i = blockIdx.x * blockDim.x + threadIdx.x;
    if (i < NRB) { g_bcnt[i] = 0; g_cur[i] = 0; }
    if (i < RR)  g_ccnt[i] = 0;
}

__global__ void k_count(const int* __restrict__ ei, const int* __restrict__ et) {
    int e = blockIdx.x * blockDim.x + threadIdx.x;
    if (e >= NE) return;
    int dst = ei[NE + e];
    int r   = et[e];
    atomicAdd(&g_bcnt[r*NN + dst], 1);
}

// exclusive scan over NRB = 625 * 1024 exactly
__global__ void k_scan1() {
    __shared__ int sh[256];
    int tid  = threadIdx.x;
    int base = blockIdx.x * 1024 + tid * 4;
    int v0 = g_bcnt[base+0], v1 = g_bcnt[base+1];
    int v2 = g_bcnt[base+2], v3 = g_bcnt[base+3];
    int tsum = v0 + v1 + v2 + v3;
    sh[tid] = tsum;
    __syncthreads();
    for (int off = 1; off < 256; off <<= 1) {
        int t = (tid >= off) ? sh[tid - off] : 0;
        __syncthreads();
        sh[tid] += t;
        __syncthreads();
    }
    int excl = sh[tid] - tsum;
    g_boff[base+0] = excl;
    g_boff[base+1] = excl + v0;
    g_boff[base+2] = excl + v0 + v1;
    g_boff[base+3] = excl + v0 + v1 + v2;
    if (tid == 255) g_bsum[blockIdx.x] = sh[255];
}

__global__ void k_scan2() {
    __shared__ int sh[1024];
    int tid = threadIdx.x;
    int v = (tid < 625) ? g_bsum[tid] : 0;
    sh[tid] = v;
    __syncthreads();
    for (int off = 1; off < 1024; off <<= 1) {
        int t = (tid >= off) ? sh[tid - off] : 0;
        __syncthreads();
        sh[tid] += t;
        __syncthreads();
    }
    if (tid < 625) g_bsumoff[tid] = sh[tid] - v;
}

__global__ void k_scan3() {
    int tid  = threadIdx.x;
    int add  = g_bsumoff[blockIdx.x];
    int base = blockIdx.x * 1024 + tid * 4;
    g_boff[base+0] += add; g_boff[base+1] += add;
    g_boff[base+2] += add; g_boff[base+3] += add;
    if (blockIdx.x == 0 && tid == 0) g_boff[NRB] = NE;  // sentinel
}

__global__ void k_fill(const int* __restrict__ ei, const int* __restrict__ et) {
    int e = blockIdx.x * blockDim.x + threadIdx.x;
    if (e >= NE) return;
    int src = ei[e];
    int dst = ei[NE + e];
    int r   = et[e];
    int b   = r*NN + dst;
    int p   = atomicAdd(&g_cur[b], 1);
    int slot = g_boff[b] + p;
    g_esrc[slot] = src;
    g_edst[slot] = dst;
}

// ---------------------------------------------------------------- compact nonempty buckets
// warp-aggregated: NN % 32 == 0 so a warp never straddles a relation boundary.
__global__ void k_compact() {
    int i = blockIdx.x * blockDim.x + threadIdx.x;
    if (i >= NRB) return;
    int r = i / NN, d = i - r*NN;
    bool f = g_bcnt[i] > 0;
    unsigned mask = __ballot_sync(0xffffffffu, f);
    if (mask == 0) return;
    int lane = threadIdx.x & 31;
    int leader = __ffs(mask) - 1;
    int base = 0;
    if (lane == leader) base = atomicAdd(&g_ccnt[r], __popc(mask));
    base = __shfl_sync(0xffffffffu, base, leader);
    if (f) {
        int rank = __popc(mask & ((1u << lane) - 1));
        g_rows[r*NN + base + rank] = d;
    }
}

// ---------------------------------------------------------------- layer 1 (fused, aggregate-first)
// Edge-parallel A-build: edges of (rel, tile) are CONTIGUOUS in g_esrc/g_edst
// (bucket-CSR order). Each edge-thread atomicAdds x[src]/deg into smem f32
// staging; no per-row serial straggler chains.
__global__ void __launch_bounds__(128, 3)
k_l1(const float* __restrict__ x,  const float* __restrict__ W1,
     const float* __restrict__ r1, const float* __restrict__ b1) {
    __shared__ float    Af[64][17];    // f32 staging (pad 17)
    __shared__ uint32_t As[64][20];
    __shared__ uint32_t Bs[16][136];
    int m0  = blockIdx.x * 64;
    int hi  = m0 + 64 < NN ? m0 + 64 : NN;
    int tid = threadIdx.x;
    int wid = tid >> 5, lane = tid & 31;
    int gr  = lane >> 2, tg = lane & 3;
    int row = tid >> 1, hf = tid & 1;
    int bk  = tid >> 3, bc = (tid & 7) << 4;

    float c[4][4][4];
    #pragma unroll
    for (int i = 0; i < 4; i++)
        #pragma unroll
        for (int j = 0; j < 4; j++)
            #pragma unroll
            for (int q = 0; q < 4; q++) c[i][j][q] = 0.f;

    for (int rel = 0; rel < 33; ++rel) {
        __syncthreads();                       // prev MMA done with As/Bs; prev convert done with Af
        // zero staging + fill B tile
        #pragma unroll
        for (int i = 0; i < 8; i++) Af[row][hf*8 + i] = 0.f;
        const float* Bsrc = (rel < 32) ? (W1 + rel*(EMB*HID)) : r1;
        #pragma unroll
        for (int i = 0; i < 4; i++) {
            float4 u = *(const float4*)&Bsrc[bk*HID + bc + i*4];
            *(uint4*)&Bs[bk][bc + i*4] = make_uint4(f2tf32(u.x), f2tf32(u.y), f2tf32(u.z), f2tf32(u.w));
        }
        __syncthreads();                       // Af zeroed
        if (rel < 32) {
            int off0 = g_boff[rel*NN + m0];
            int off1 = g_boff[rel*NN + hi];
            for (int i = off0 + tid; i < off1; i += 128) {
                int src = g_esrc[i];
                int dst = g_edst[i];
                int rr  = dst - m0;
                float iv = 1.f / (float)g_bcnt[rel*NN + dst];
                const float4* p = (const float4*)&x[src*EMB];
                float4 a = p[0], b4 = p[1], c4 = p[2], d4 = p[3];
                atomicAdd(&Af[rr][ 0], a.x*iv);  atomicAdd(&Af[rr][ 1], a.y*iv);
                atomicAdd(&Af[rr][ 2], a.z*iv);  atomicAdd(&Af[rr][ 3], a.w*iv);
                atomicAdd(&Af[rr][ 4], b4.x*iv); atomicAdd(&Af[rr][ 5], b4.y*iv);
                atomicAdd(&Af[rr][ 6], b4.z*iv); atomicAdd(&Af[rr][ 7], b4.w*iv);
                atomicAdd(&Af[rr][ 8], c4.x*iv); atomicAdd(&Af[rr][ 9], c4.y*iv);
                atomicAdd(&Af[rr][10], c4.z*iv); atomicAdd(&Af[rr][11], c4.w*iv);
                atomicAdd(&Af[rr][12], d4.x*iv); atomicAdd(&Af[rr][13], d4.y*iv);
                atomicAdd(&Af[rr][14], d4.z*iv); atomicAdd(&Af[rr][15], d4.w*iv);
            }
        } else {
            int n = m0 + row;
            if (n < NN) {
                const float4* p = (const float4*)&x[n*EMB + hf*8];
                float4 a = p[0], b4 = p[1];
                Af[row][hf*8+0]=a.x;  Af[row][hf*8+1]=a.y;
                Af[row][hf*8+2]=a.z;  Af[row][hf*8+3]=a.w;
                Af[row][hf*8+4]=b4.x; Af[row][hf*8+5]=b4.y;
                Af[row][hf*8+6]=b4.z; Af[row][hf*8+7]=b4.w;
            }
        }
        __syncthreads();                       // scatter done
        #pragma unroll
        for (int i = 0; i < 8; i++) As[row][hf*8 + i] = f2tf32(Af[row][hf*8 + i]);
        __syncthreads();                       // As ready
        #pragma unroll
        for (int kc = 0; kc < 2; ++kc) {
            int k0 = kc << 3;
            uint32_t a[4][4], b[4][2];
            #pragma unroll
            for (int mt = 0; mt < 4; ++mt) {
                int mr = mt*16;
                a[mt][0] = As[mr+gr  ][k0+tg  ];
                a[mt][1] = As[mr+gr+8][k0+tg  ];
                a[mt][2] = As[mr+gr  ][k0+tg+4];
                a[mt][3] = As[mr+gr+8][k0+tg+4];
            }
            #pragma unroll
            for (int nt = 0; nt < 4; ++nt) {
                int nc = wid*32 + nt*8 + gr;
                b[nt][0] = Bs[k0+tg  ][nc];
                b[nt][1] = Bs[k0+tg+4][nc];
            }
            #pragma unroll
            for (int mt = 0; mt < 4; ++mt)
                #pragma unroll
                for (int nt = 0; nt < 4; ++nt)
                    mma_tf32(c[mt][nt], a[mt], b[nt]);
        }
    }
    #pragma unroll
    for (int mt = 0; mt < 4; ++mt) {
        #pragma unroll
        for (int eh = 0; eh < 2; ++eh) {
            int rn = m0 + mt*16 + gr + eh*8;
            if (rn < NN) {
                #pragma unroll
                for (int nt = 0; nt < 4; ++nt) {
                    int col = wid*32 + nt*8 + tg*2;
                    float v0 = c[mt][nt][eh*2+0] + b1[col];
                    float v1 = c[mt][nt][eh*2+1] + b1[col+1];
                    *(float2*)&g_h1[rn*HID + col] =
                        make_float2(fmaxf(v0, 0.f), fmaxf(v1, 0.f));
                }
            }
        }
    }
}

// ---------------------------------------------------------------- layer-2 root: out = h1 @ root2 + b2
// Plain store — initializes out before k_l2agg's atomic adds (stream-ordered).
__global__ void __launch_bounds__(128)
k_root(const float* __restrict__ r2, const float* __restrict__ b2,
       float* __restrict__ out) {
    __shared__ uint32_t As[64][132];
    __shared__ uint32_t Bs[16][136];
    int m0  = blockIdx.x * 64;
    int tid = threadIdx.x;
    int wid = tid >> 5, lane = tid & 31;
    int gr  = lane >> 2, tg = lane & 3;
    int row = tid >> 1, hf = tid & 1;
    int n   = m0 + row;
    int bk  = tid >> 3, bc = (tid & 7) << 4;

    float c[4][4][4];
    #pragma unroll
    for (int i = 0; i < 4; i++)
        #pragma unroll
        for (int j = 0; j < 4; j++)
            #pragma unroll
            for (int q = 0; q < 4; q++) c[i][j][q] = 0.f;

    #pragma unroll
    for (int hp = 0; hp < 2; ++hp) {
        int cbase = hf*64 + hp*32;
        float4 s[8];
        #pragma unroll
        for (int i = 0; i < 8; i++) s[i] = make_float4(0.f,0.f,0.f,0.f);
        if (n < NN) {
            const float4* p = (const float4*)&g_h1[n*HID + cbase];
            #pragma unroll
            for (int i = 0; i < 8; i++) s[i] = p[i];
        }
        #pragma unroll
        for (int i = 0; i < 8; i++)
            *(uint4*)&As[row][cbase + i*4] =
                make_uint4(f2tf32(s[i].x), f2tf32(s[i].y), f2tf32(s[i].z), f2tf32(s[i].w));
    }

    for (int step = 0; step < 8; ++step) {
        __syncthreads();
        const float* Bsrc = r2 + step*16*HID;
        #pragma unroll
        for (int i = 0; i < 4; i++) {
            float4 u = *(const float4*)&Bsrc[bk*HID + bc + i*4];
            *(uint4*)&Bs[bk][bc + i*4] = make_uint4(f2tf32(u.x), f2tf32(u.y), f2tf32(u.z), f2tf32(u.w));
        }
        __syncthreads();
        #pragma unroll
        for (int kc = 0; kc < 2; ++kc) {
            int k0 = kc << 3;
            int ac = step*16 + k0;
            uint32_t a[4][4], b[4][2];
            #pragma unroll
            for (int mt = 0; mt < 4; ++mt) {
                int mr = mt*16;
                a[mt][0] = As[mr+gr  ][ac+tg  ];
                a[mt][1] = As[mr+gr+8][ac+tg  ];
                a[mt][2] = As[mr+gr  ][ac+tg+4];
                a[mt][3] = As[mr+gr+8][ac+tg+4];
            }
            #pragma unroll
            for (int nt = 0; nt < 4; ++nt) {
                int nc = wid*32 + nt*8 + gr;
                b[nt][0] = Bs[k0+tg  ][nc];
                b[nt][1] = Bs[k0+tg+4][nc];
            }
            #pragma unroll
            for (int mt = 0; mt < 4; ++mt)
                #pragma unroll
                for (int nt = 0; nt < 4; ++nt)
                    mma_tf32(c[mt][nt], a[mt], b[nt]);
        }
    }

    #pragma unroll
    for (int mt = 0; mt < 4; ++mt) {
        #pragma unroll
        for (int eh = 0; eh < 2; ++eh) {
            int rn = m0 + mt*16 + gr + eh*8;
            if (rn < NN) {
                #pragma unroll
                for (int nt = 0; nt < 4; ++nt) {
                    int col = wid*32 + nt*8 + tg*2;
                    *(float2*)&out[rn*HID + col] =
                        make_float2(c[mt][nt][eh*2+0] + b2[col],
                                    c[mt][nt][eh*2+1] + b2[col+1]);
                }
            }
        }
    }
}

// ---------------------------------------------------------------- layer-2 relation GEMM (compacted)
// grid (313, 32): block = 64 compacted (rel, dst) buckets of one relation.
__global__ void __launch_bounds__(128)
k_l2agg(const float* __restrict__ W2, float* __restrict__ out) {
    __shared__ uint32_t As[64][132];
    __shared__ uint32_t Bs[16][136];
    int rel = blockIdx.y;
    int m0  = blockIdx.x * 64;
    int cnt = g_ccnt[rel];
    if (m0 >= cnt) return;
    const int* rows = g_rows + rel*NN;

    int tid = threadIdx.x;
    int wid = tid >> 5, lane = tid & 31;
    int gr  = lane >> 2, tg = lane & 3;
    int row = tid >> 1, hf = tid & 1;
    int idx = m0 + row;
    int d   = (idx < cnt) ? rows[idx] : -1;
    int bk  = tid >> 3, bc = (tid & 7) << 4;

    float c[4][4][4];
    #pragma unroll
    for (int i = 0; i < 4; i++)
        #pragma unroll
        for (int j = 0; j < 4; j++)
            #pragma unroll
            for (int q = 0; q < 4; q++) c[i][j][q] = 0.f;

    int deg = 0, off = 0;
    if (d >= 0) { int b = rel*NN + d; deg = g_bcnt[b]; off = g_boff[b]; }
    #pragma unroll
    for (int hp = 0; hp < 2; ++hp) {
        int cbase = hf*64 + hp*32;
        float4 s[8];
        #pragma unroll
        for (int i = 0; i < 8; i++) s[i] = make_float4(0.f,0.f,0.f,0.f);
        for (int j = 0; j < deg; ++j) {
            int src = g_esrc[off + j];
            const float4* p = (const float4*)&g_h1[src*HID + cbase];
            #pragma unroll
            for (int i = 0; i < 8; i++) {
                float4 a = p[i];
                s[i].x += a.x; s[i].y += a.y; s[i].z += a.z; s[i].w += a.w;
            }
        }
        if (deg > 0) {
            float iv = 1.f / (float)deg;
            #pragma unroll
            for (int i = 0; i < 8; i++) { s[i].x*=iv; s[i].y*=iv; s[i].z*=iv; s[i].w*=iv; }
        }
        #pragma unroll
        for (int i = 0; i < 8; i++)
            *(uint4*)&As[row][cbase + i*4] =
                make_uint4(f2tf32(s[i].x), f2tf32(s[i].y), f2tf32(s[i].z), f2tf32(s[i].w));
    }

    const float* Bbase = W2 + rel*(HID*HID);
    for (int step = 0; step < 8; ++step) {
        __syncthreads();
        const float* Bsrc = Bbase + step*16*HID;
        #pragma unroll
        for (int i = 0; i < 4; i++) {
            float4 u = *(const float4*)&Bsrc[bk*HID + bc + i*4];
            *(uint4*)&Bs[bk][bc + i*4] = make_uint4(f2tf32(u.x), f2tf32(u.y), f2tf32(u.z), f2tf32(u.w));
        }
        __syncthreads();
        #pragma unroll
        for (int kc = 0; kc < 2; ++kc) {
            int k0 = kc << 3;
            int ac = step*16 + k0;
            uint32_t a[4][4], b[4][2];
            #pragma unroll
            for (int mt = 0; mt < 4; ++mt) {
                int mr = mt*16;
                a[mt][0] = As[mr+gr  ][ac+tg  ];
                a[mt][1] = As[mr+gr+8][ac+tg  ];
                a[mt][2] = As[mr+gr  ][ac+tg+4];
                a[mt][3] = As[mr+gr+8][ac+tg+4];
            }
            #pragma unroll
            for (int nt = 0; nt < 4; ++nt) {
                int nc = wid*32 + nt*8 + gr;
                b[nt][0] = Bs[k0+tg  ][nc];
                b[nt][1] = Bs[k0+tg+4][nc];
            }
            #pragma unroll
            for (int mt = 0; mt < 4; ++mt)
                #pragma unroll
                for (int nt = 0; nt < 4; ++nt)
                    mma_tf32(c[mt][nt], a[mt], b[nt]);
        }
    }

    // ---- epilogue: vector reductions into out[dst] (L2-resident, 10 MB)
    #pragma unroll
    for (int mt = 0; mt < 4; ++mt) {
        #pragma unroll
        for (int eh = 0; eh < 2; ++eh) {
            int i2 = m0 + mt*16 + gr + eh*8;
            if (i2 < cnt) {
                int d2 = rows[i2];
                float* ob = &out[d2*HID];
                #pragma unroll
                for (int nt = 0; nt < 4; ++nt) {
                    int col = wid*32 + nt*8 + tg*2;
                    red_add_v2(&ob[col], c[mt][nt][eh*2+0], c[mt][nt][eh*2+1]);
                }
            }
        }
    }
}

// ---------------------------------------------------------------- launch
extern "C" void kernel_launch(void* const* d_in, const int* in_sizes, int n_in,
                              void* d_out, int out_size) {
    const int* ei    = (const int*)d_in[0];            // edge_index [2, E] int32
    const int* et    = (const int*)d_in[1];            // edge_type  [E]    int32
    const float* x   = (const float*)d_in[2];          // node_emb [N, 16]
    const float* W1  = (const float*)d_in[3];          // [32, 16, 128]
    const float* r1  = (const float*)d_in[4];          // [16, 128]
    const float* b1  = (const float*)d_in[5];          // [128]
    const float* W2  = (const float*)d_in[6];          // [32, 128, 128]
    const float* r2  = (const float*)d_in[7];          // [128, 128]
    const float* b2  = (const float*)d_in[8];          // [128]
    float* out = (float*)d_out;                        // [20000, 128]

    k_zero   <<<(NRB + 255)/256, 256>>>();
    k_count  <<<(NE + 255)/256, 256>>>(ei, et);
    k_scan1  <<<625, 256>>>();
    k_scan2  <<<1, 1024>>>();
    k_scan3  <<<625, 256>>>();
    k_fill   <<<(NE + 255)/256, 256>>>(ei, et);
    k_compact<<<(NRB + 255)/256, 256>>>();
    k_l1     <<<NTILE, 128>>>(x, W1, r1, b1);
    k_root   <<<NTILE, 128>>>(r2, b2, out);
    dim3 g2(NTILE, RR);
    k_l2agg  <<<g2, 128>>>(W2, out);
}

// round 15
// speedup vs baseline: 1.8889x; 1.4159x over previous
#include <cuda_runtime.h>
#include <cstdint>

#define NN   20000
#define RR   32
#define EMB  16
#define HID  128
#define NE   600000
#define NRB  (NN*RR)          // 640000 (rel, dst) buckets, r-major: b = r*NN + dst
#define NTILE 313             // ceil(NN/64)
#define MT2  157              // ceil(NN/128) for 128-row layer-2 tiles

// ---- scratch (device globals; no allocation anywhere) ----
__device__ int   g_bcnt[NRB];     // edges per (rel, dst) bucket
__device__ int   g_cur [NRB];     // fill cursor
__device__ int   g_boff[NRB];     // exclusive prefix (CSR offsets)
__device__ int   g_bsum[1024];    // scan partials
__device__ int   g_bsumoff[1024];
__device__ int   g_esrc[NE];      // src ids grouped by bucket
__device__ float g_h1  [NN*HID];  // layer-1 output (10 MB, L2-resident)
__device__ int   g_ccnt[RR];      // nonempty-bucket count per relation
__device__ int   g_rows[RR*NN];   // per-rel compacted dst lists

// ---------------------------------------------------------------- helpers
__device__ __forceinline__ uint32_t f2tf32(float f) {
    uint32_t r;
    asm("cvt.rna.tf32.f32 %0, %1;" : "=r"(r) : "f"(f));
    return r;
}

__device__ __forceinline__ void mma_tf32(float* d, const uint32_t* a, const uint32_t* b) {
    asm volatile("mma.sync.aligned.m16n8k8.row.col.f32.tf32.tf32.f32 "
                 "{%0,%1,%2,%3}, {%4,%5,%6,%7}, {%8,%9}, {%0,%1,%2,%3};"
                 : "+f"(d[0]), "+f"(d[1]), "+f"(d[2]), "+f"(d[3])
                 : "r"(a[0]), "r"(a[1]), "r"(a[2]), "r"(a[3]),
                   "r"(b[0]), "r"(b[1]));
}

__device__ __forceinline__ void red_add_v2(float* p, float a, float b) {
    asm volatile("red.global.add.v2.f32 [%0], {%1, %2};"
                 :: "l"(p), "f"(a), "f"(b) : "memory");
}

// ---------------------------------------------------------------- CSR build
__global__ void k_zero() {
    int i = blockIdx.x * blockDim.x + threadIdx.x;
    if (i < NRB) { g_bcnt[i] = 0; g_cur[i] = 0; }
    if (i < RR)  g_ccnt[i] = 0;
}

__global__ void k_count(const int* __restrict__ ei, const int* __restrict__ et) {
    int e = blockIdx.x * blockDim.x + threadIdx.x;
    if (e >= NE) return;
    int dst = ei[NE + e];
    int r   = et[e];
    atomicAdd(&g_bcnt[r*NN + dst], 1);
}

// exclusive scan over NRB = 625 * 1024 exactly
__global__ void k_scan1() {
    __shared__ int sh[256];
    int tid  = threadIdx.x;
    int base = blockIdx.x * 1024 + tid * 4;
    int v0 = g_bcnt[base+0], v1 = g_bcnt[base+1];
    int v2 = g_bcnt[base+2], v3 = g_bcnt[base+3];
    int tsum = v0 + v1 + v2 + v3;
    sh[tid] = tsum;
    __syncthreads();
    for (int off = 1; off < 256; off <<= 1) {
        int t = (tid >= off) ? sh[tid - off] : 0;
        __syncthreads();
        sh[tid] += t;
        __syncthreads();
    }
    int excl = sh[tid] - tsum;
    g_boff[base+0] = excl;
    g_boff[base+1] = excl + v0;
    g_boff[base+2] = excl + v0 + v1;
    g_boff[base+3] = excl + v0 + v1 + v2;
    if (tid == 255) g_bsum[blockIdx.x] = sh[255];
}

__global__ void k_scan2() {
    __shared__ int sh[1024];
    int tid = threadIdx.x;
    int v = (tid < 625) ? g_bsum[tid] : 0;
    sh[tid] = v;
    __syncthreads();
    for (int off = 1; off < 1024; off <<= 1) {
        int t = (tid >= off) ? sh[tid - off] : 0;
        __syncthreads();
        sh[tid] += t;
        __syncthreads();
    }
    if (tid < 625) g_bsumoff[tid] = sh[tid] - v;
}

__global__ void k_scan3() {
    int tid  = threadIdx.x;
    int add  = g_bsumoff[blockIdx.x];
    int base = blockIdx.x * 1024 + tid * 4;
    g_boff[base+0] += add; g_boff[base+1] += add;
    g_boff[base+2] += add; g_boff[base+3] += add;
}

__global__ void k_fill(const int* __restrict__ ei, const int* __restrict__ et) {
    int e = blockIdx.x * blockDim.x + threadIdx.x;
    if (e >= NE) return;
    int src = ei[e];
    int dst = ei[NE + e];
    int r   = et[e];
    int b   = r*NN + dst;
    int p   = atomicAdd(&g_cur[b], 1);
    g_esrc[g_boff[b] + p] = src;
}

// ---------------------------------------------------------------- compact nonempty buckets
// warp-aggregated: NN % 32 == 0 so a warp never straddles a relation boundary.
__global__ void k_compact() {
    int i = blockIdx.x * blockDim.x + threadIdx.x;
    if (i >= NRB) return;
    int r = i / NN, d = i - r*NN;
    bool f = g_bcnt[i] > 0;
    unsigned mask = __ballot_sync(0xffffffffu, f);
    if (mask == 0) return;
    int lane = threadIdx.x & 31;
    int leader = __ffs(mask) - 1;
    int base = 0;
    if (lane == leader) base = atomicAdd(&g_ccnt[r], __popc(mask));
    base = __shfl_sync(0xffffffffu, base, leader);
    if (f) {
        int rank = __popc(mask & ((1u << lane) - 1));
        g_rows[r*NN + base + rank] = d;
    }
}

// ---------------------------------------------------------------- layer 1 (fused, aggregate-first)
// R12 version: serial per-row bucket gather (mean deg 1.54), 33 fused rel GEMMs.
__global__ void __launch_bounds__(128, 3)
k_l1(const float* __restrict__ x,  const float* __restrict__ W1,
     const float* __restrict__ r1, const float* __restrict__ b1) {
    __shared__ uint32_t As[64][20];
    __shared__ uint32_t Bs[16][136];
    int m0  = blockIdx.x * 64;
    int tid = threadIdx.x;
    int wid = tid >> 5, lane = tid & 31;
    int gr  = lane >> 2, tg = lane & 3;
    int row = tid >> 1, hf = tid & 1;
    int n   = m0 + row;
    int bk  = tid >> 3, bc = (tid & 7) << 4;

    float c[4][4][4];
    #pragma unroll
    for (int i = 0; i < 4; i++)
        #pragma unroll
        for (int j = 0; j < 4; j++)
            #pragma unroll
            for (int q = 0; q < 4; q++) c[i][j][q] = 0.f;

    for (int rel = 0; rel < 33; ++rel) {
        __syncthreads();
        float4 s0 = make_float4(0.f,0.f,0.f,0.f), s1 = s0;
        if (n < NN) {
            if (rel < 32) {
                int b = rel*NN + n;
                int deg = g_bcnt[b], off = g_boff[b];
                for (int j = 0; j < deg; ++j) {
                    int src = g_esrc[off + j];
                    const float4* p = (const float4*)&x[src*EMB + hf*8];
                    float4 a = p[0], bq = p[1];
                    s0.x += a.x;  s0.y += a.y;  s0.z += a.z;  s0.w += a.w;
                    s1.x += bq.x; s1.y += bq.y; s1.z += bq.z; s1.w += bq.w;
                }
                if (deg > 0) {
                    float iv = 1.f / (float)deg;
                    s0.x*=iv; s0.y*=iv; s0.z*=iv; s0.w*=iv;
                    s1.x*=iv; s1.y*=iv; s1.z*=iv; s1.w*=iv;
                }
            } else {
                const float4* p = (const float4*)&x[n*EMB + hf*8];
                s0 = p[0]; s1 = p[1];
            }
        }
        *(uint4*)&As[row][hf*8    ] = make_uint4(f2tf32(s0.x), f2tf32(s0.y), f2tf32(s0.z), f2tf32(s0.w));
        *(uint4*)&As[row][hf*8 + 4] = make_uint4(f2tf32(s1.x), f2tf32(s1.y), f2tf32(s1.z), f2tf32(s1.w));
        const float* Bsrc = (rel < 32) ? (W1 + rel*(EMB*HID)) : r1;
        #pragma unroll
        for (int i = 0; i < 4; i++) {
            float4 u = *(const float4*)&Bsrc[bk*HID + bc + i*4];
            *(uint4*)&Bs[bk][bc + i*4] = make_uint4(f2tf32(u.x), f2tf32(u.y), f2tf32(u.z), f2tf32(u.w));
        }
        __syncthreads();
        #pragma unroll
        for (int kc = 0; kc < 2; ++kc) {
            int k0 = kc << 3;
            uint32_t a[4][4], b[4][2];
            #pragma unroll
            for (int mt = 0; mt < 4; ++mt) {
                int mr = mt*16;
                a[mt][0] = As[mr+gr  ][k0+tg  ];
                a[mt][1] = As[mr+gr+8][k0+tg  ];
                a[mt][2] = As[mr+gr  ][k0+tg+4];
                a[mt][3] = As[mr+gr+8][k0+tg+4];
            }
            #pragma unroll
            for (int nt = 0; nt < 4; ++nt) {
                int nc = wid*32 + nt*8 + gr;
                b[nt][0] = Bs[k0+tg  ][nc];
                b[nt][1] = Bs[k0+tg+4][nc];
            }
            #pragma unroll
            for (int mt = 0; mt < 4; ++mt)
                #pragma unroll
                for (int nt = 0; nt < 4; ++nt)
                    mma_tf32(c[mt][nt], a[mt], b[nt]);
        }
    }
    #pragma unroll
    for (int mt = 0; mt < 4; ++mt) {
        #pragma unroll
        for (int eh = 0; eh < 2; ++eh) {
            int rn = m0 + mt*16 + gr + eh*8;
            if (rn < NN) {
                #pragma unroll
                for (int nt = 0; nt < 4; ++nt) {
                    int col = wid*32 + nt*8 + tg*2;
                    float v0 = c[mt][nt][eh*2+0] + b1[col];
                    float v1 = c[mt][nt][eh*2+1] + b1[col+1];
                    *(float2*)&g_h1[rn*HID + col] =
                        make_float2(fmaxf(v0, 0.f), fmaxf(v1, 0.f));
                }
            }
        }
    }
}

// ---------------------------------------------------------------- layer-2 root: out = h1 @ root2 + b2
__global__ void __launch_bounds__(128)
k_root(const float* __restrict__ r2, const float* __restrict__ b2,
       float* __restrict__ out) {
    __shared__ uint32_t As[64][132];
    __shared__ uint32_t Bs[16][136];
    int m0  = blockIdx.x * 64;
    int tid = threadIdx.x;
    int wid = tid >> 5, lane = tid & 31;
    int gr  = lane >> 2, tg = lane & 3;
    int row = tid >> 1, hf = tid & 1;
    int n   = m0 + row;
    int bk  = tid >> 3, bc = (tid & 7) << 4;

    float c[4][4][4];
    #pragma unroll
    for (int i = 0; i < 4; i++)
        #pragma unroll
        for (int j = 0; j < 4; j++)
            #pragma unroll
            for (int q = 0; q < 4; q++) c[i][j][q] = 0.f;

    #pragma unroll
    for (int hp = 0; hp < 2; ++hp) {
        int cbase = hf*64 + hp*32;
        float4 s[8];
        #pragma unroll
        for (int i = 0; i < 8; i++) s[i] = make_float4(0.f,0.f,0.f,0.f);
        if (n < NN) {
            const float4* p = (const float4*)&g_h1[n*HID + cbase];
            #pragma unroll
            for (int i = 0; i < 8; i++) s[i] = p[i];
        }
        #pragma unroll
        for (int i = 0; i < 8; i++)
            *(uint4*)&As[row][cbase + i*4] =
                make_uint4(f2tf32(s[i].x), f2tf32(s[i].y), f2tf32(s[i].z), f2tf32(s[i].w));
    }

    for (int step = 0; step < 8; ++step) {
        __syncthreads();
        const float* Bsrc = r2 + step*16*HID;
        #pragma unroll
        for (int i = 0; i < 4; i++) {
            float4 u = *(const float4*)&Bsrc[bk*HID + bc + i*4];
            *(uint4*)&Bs[bk][bc + i*4] = make_uint4(f2tf32(u.x), f2tf32(u.y), f2tf32(u.z), f2tf32(u.w));
        }
        __syncthreads();
        #pragma unroll
        for (int kc = 0; kc < 2; ++kc) {
            int k0 = kc << 3;
            int ac = step*16 + k0;
            uint32_t a[4][4], b[4][2];
            #pragma unroll
            for (int mt = 0; mt < 4; ++mt) {
                int mr = mt*16;
                a[mt][0] = As[mr+gr  ][ac+tg  ];
                a[mt][1] = As[mr+gr+8][ac+tg  ];
                a[mt][2] = As[mr+gr  ][ac+tg+4];
                a[mt][3] = As[mr+gr+8][ac+tg+4];
            }
            #pragma unroll
            for (int nt = 0; nt < 4; ++nt) {
                int nc = wid*32 + nt*8 + gr;
                b[nt][0] = Bs[k0+tg  ][nc];
                b[nt][1] = Bs[k0+tg+4][nc];
            }
            #pragma unroll
            for (int mt = 0; mt < 4; ++mt)
                #pragma unroll
                for (int nt = 0; nt < 4; ++nt)
                    mma_tf32(c[mt][nt], a[mt], b[nt]);
        }
    }

    #pragma unroll
    for (int mt = 0; mt < 4; ++mt) {
        #pragma unroll
        for (int eh = 0; eh < 2; ++eh) {
            int rn = m0 + mt*16 + gr + eh*8;
            if (rn < NN) {
                #pragma unroll
                for (int nt = 0; nt < 4; ++nt) {
                    int col = wid*32 + nt*8 + tg*2;
                    *(float2*)&out[rn*HID + col] =
                        make_float2(c[mt][nt][eh*2+0] + b2[col],
                                    c[mt][nt][eh*2+1] + b2[col+1]);
                }
            }
        }
    }
}

// ---------------------------------------------------------------- layer-2 relation GEMM (compacted)
// 128-row tiles, 256 threads, 8 warps (4 in M x 2 in N), warp tile 32x64.
// Dynamic smem: As[128][132] + Bs[16][136] (uint32) = 76288 bytes.
#define AS(r, c) smem_l2[(r)*132 + (c)]
#define BS(r, c) smem_l2[128*132 + (r)*136 + (c)]

__global__ void __launch_bounds__(256)
k_l2agg(const float* __restrict__ W2, float* __restrict__ out) {
    extern __shared__ uint32_t smem_l2[];
    int rel = blockIdx.y;
    int m0  = blockIdx.x * 128;
    int cnt = g_ccnt[rel];
    if (m0 >= cnt) return;
    const int* rows = g_rows + rel*NN;

    int tid = threadIdx.x;
    int wid = tid >> 5, lane = tid & 31;
    int wm  = wid & 3,  wn   = wid >> 2;
    int gr  = lane >> 2, tg = lane & 3;
    int row = tid >> 1, hf = tid & 1;
    int idx = m0 + row;
    int d   = (idx < cnt) ? rows[idx] : -1;
    int bk  = tid >> 4, bc = (tid & 15) << 3;

    float c[2][8][4];
    #pragma unroll
    for (int i = 0; i < 2; i++)
        #pragma unroll
        for (int j = 0; j < 8; j++)
            #pragma unroll
            for (int q = 0; q < 4; q++) c[i][j][q] = 0.f;

    // ---- A build: mean of h1[src] over bucket (rel, d); deg >= 1 for valid rows
    int deg = 0, off = 0;
    if (d >= 0) { int b = rel*NN + d; deg = g_bcnt[b]; off = g_boff[b]; }
    #pragma unroll
    for (int hp = 0; hp < 2; ++hp) {
        int cbase = hf*64 + hp*32;
        float4 s[8];
        #pragma unroll
        for (int i = 0; i < 8; i++) s[i] = make_float4(0.f,0.f,0.f,0.f);
        for (int j = 0; j < deg; ++j) {
            int src = g_esrc[off + j];
            const float4* p = (const float4*)&g_h1[src*HID + cbase];
            #pragma unroll
            for (int i = 0; i < 8; i++) {
                float4 a = p[i];
                s[i].x += a.x; s[i].y += a.y; s[i].z += a.z; s[i].w += a.w;
            }
        }
        if (deg > 0) {
            float iv = 1.f / (float)deg;
            #pragma unroll
            for (int i = 0; i < 8; i++) { s[i].x*=iv; s[i].y*=iv; s[i].z*=iv; s[i].w*=iv; }
        }
        #pragma unroll
        for (int i = 0; i < 8; i++)
            *(uint4*)&AS(row, cbase + i*4) =
                make_uint4(f2tf32(s[i].x), f2tf32(s[i].y), f2tf32(s[i].z), f2tf32(s[i].w));
    }

    const float* Bbase = W2 + rel*(HID*HID);
    for (int step = 0; step < 8; ++step) {
        __syncthreads();
        const float* Bsrc = Bbase + step*16*HID;
        {
            float4 u0 = *(const float4*)&Bsrc[bk*HID + bc];
            float4 u1 = *(const float4*)&Bsrc[bk*HID + bc + 4];
            *(uint4*)&BS(bk, bc    ) = make_uint4(f2tf32(u0.x), f2tf32(u0.y), f2tf32(u0.z), f2tf32(u0.w));
            *(uint4*)&BS(bk, bc + 4) = make_uint4(f2tf32(u1.x), f2tf32(u1.y), f2tf32(u1.z), f2tf32(u1.w));
        }
        __syncthreads();
        #pragma unroll
        for (int kc = 0; kc < 2; ++kc) {
            int k0 = kc << 3;
            int ac = step*16 + k0;
            uint32_t a[2][4], b[8][2];
            #pragma unroll
            for (int mt = 0; mt < 2; ++mt) {
                int mr = wm*32 + mt*16;
                a[mt][0] = AS(mr+gr  , ac+tg  );
                a[mt][1] = AS(mr+gr+8, ac+tg  );
                a[mt][2] = AS(mr+gr  , ac+tg+4);
                a[mt][3] = AS(mr+gr+8, ac+tg+4);
            }
            #pragma unroll
            for (int nt = 0; nt < 8; ++nt) {
                int nc = wn*64 + nt*8 + gr;
                b[nt][0] = BS(k0+tg  , nc);
                b[nt][1] = BS(k0+tg+4, nc);
            }
            #pragma unroll
            for (int mt = 0; mt < 2; ++mt)
                #pragma unroll
                for (int nt = 0; nt < 8; ++nt)
                    mma_tf32(c[mt][nt], a[mt], b[nt]);
        }
    }

    // ---- epilogue: vector reductions into out[dst] (L2-resident, 10 MB)
    #pragma unroll
    for (int mt = 0; mt < 2; ++mt) {
        #pragma unroll
        for (int eh = 0; eh < 2; ++eh) {
            int i2 = m0 + wm*32 + mt*16 + gr + eh*8;
            if (i2 < cnt) {
                int d2 = rows[i2];
                float* ob = &out[d2*HID];
                #pragma unroll
                for (int nt = 0; nt < 8; ++nt) {
                    int col = wn*64 + nt*8 + tg*2;
                    red_add_v2(&ob[col], c[mt][nt][eh*2+0], c[mt][nt][eh*2+1]);
                }
            }
        }
    }
}

// ---------------------------------------------------------------- launch
extern "C" void kernel_launch(void* const* d_in, const int* in_sizes, int n_in,
                              void* d_out, int out_size) {
    const int* ei    = (const int*)d_in[0];            // edge_index [2, E] int32
    const int* et    = (const int*)d_in[1];            // edge_type  [E]    int32
    const float* x   = (const float*)d_in[2];          // node_emb [N, 16]
    const float* W1  = (const float*)d_in[3];          // [32, 16, 128]
    const float* r1  = (const float*)d_in[4];          // [16, 128]
    const float* b1  = (const float*)d_in[5];          // [128]
    const float* W2  = (const float*)d_in[6];          // [32, 128, 128]
    const float* r2  = (const float*)d_in[7];          // [128, 128]
    const float* b2  = (const float*)d_in[8];          // [128]
    float* out = (float*)d_out;                        // [20000, 128]

    const int smem_l2_bytes = (128*132 + 16*136) * 4;  // 76288
    cudaFuncSetAttribute(k_l2agg, cudaFuncAttributeMaxDynamicSharedMemorySize, smem_l2_bytes);

    k_zero   <<<(NRB + 255)/256, 256>>>();
    k_count  <<<(NE + 255)/256, 256>>>(ei, et);
    k_scan1  <<<625, 256>>>();
    k_scan2  <<<1, 1024>>>();
    k_scan3  <<<625, 256>>>();
    k_fill   <<<(NE + 255)/256, 256>>>(ei, et);
    k_compact<<<(NRB + 255)/256, 256>>>();
    k_l1     <<<NTILE, 128>>>(x, W1, r1, b1);
    k_root   <<<NTILE, 128>>>(r2, b2, out);
    dim3 g2(MT2, RR);
    k_l2agg  <<<g2, 256, smem_l2_bytes>>>(W2, out);
}